// round 6
// baseline (speedup 1.0000x reference)
#include <cuda_runtime.h>

// YOLO-style detection loss — smem-staged gather version.
// preds:  (n, 1470) f32  [pcls 980 | pconf 98 | pbox 392]
// labels: (n, 1225) f32  per cell (25 floats): [flag | 20 cls | 4 box]
// Rows are only 8B-aligned; obj-cell data is gathered with 16B-aligned
// float4 windows (≤12B overread past logical region, safe within cudaMalloc
// granularity) and scatter-clipped into shared memory.

#define L_CELLS 49
#define ROW_P 1470
#define ROW_L 1225
#define NOOBJ_W 0.5f
#define OBJ_W 0.5f
#define CLS_W 0.5f
#define COORD_W 2.5f

#define THREADS 256
#define CPT 2
#define CPB (THREADS * CPT)        // 512 cells per block
#define NWARPS (THREADS / 32)
#define MAX_ROWS 12                // rows spanned by 512 cells (<= 11) + pad
#define CHUNK 128                  // staged obj cells per pass
#define CELL_W 53                  // 25 label + 20 pcls + 8 pbox (gcd(53,32)=1)
#define MAX_BLOCKS 32768

__device__ double   g_partials[MAX_BLOCKS];
__device__ unsigned g_counter = 0;   // self-wrapping; replay-safe

__global__ void __launch_bounds__(THREADS) yolo_loss_kernel(
    const float* __restrict__ preds,
    const float* __restrict__ labels,
    int total_cells,
    int nlab_floats,
    int npred_floats,
    float* __restrict__ out)
{
    __shared__ float  s_conf[MAX_ROWS][2 * L_CELLS];
    __shared__ float  s_cell[CHUNK][CELL_W];
    __shared__ int    s_idx[CPB];
    __shared__ int    s_wcnt[NWARPS];
    __shared__ double s_red[NWARPS];
    __shared__ bool   s_last;

    const int tid  = threadIdx.x;
    const int lane = tid & 31;
    const int wid  = tid >> 5;
    const int base = blockIdx.x * CPB;
    const unsigned lmask = (1u << lane) - 1u;

    const int cmax   = min(base + CPB, total_cells);
    const int rfirst = base / L_CELLS;
    const int rlast  = (cmax - 1) / L_CELLS;
    const int nrows  = rlast - rfirst + 1;

    // ---- stage pconf for all spanned rows (coalesced float2) --------------
    for (int f = tid; f < nrows * L_CELLS; f += THREADS) {
        int r = f / L_CELLS, c = f - r * L_CELLS;
        float2 v = __ldg(reinterpret_cast<const float2*>(
            preds + (size_t)(rfirst + r) * ROW_P + 980 + 2 * c));
        s_conf[r][2 * c]     = v.x;
        s_conf[r][2 * c + 1] = v.y;
    }

    // ---- phase 1: flags (scattered, mandatory) -----------------------------
    float flag[CPT];
    int   ridx[CPT], lidx[CPT];
    #pragma unroll
    for (int k = 0; k < CPT; k++) {
        int cell = base + k * THREADS + tid;
        bool valid = cell < total_cells;
        int c = valid ? cell : base;
        int i = c / L_CELLS, l = c - (c / L_CELLS) * L_CELLS;
        ridx[k] = i - rfirst;
        lidx[k] = l;
        flag[k] = valid ? __ldg(labels + (size_t)i * ROW_L + 25 * l) : 0.0f;
    }
    __syncthreads();   // s_conf ready

    float vbase = 0.0f;
    unsigned bal[CPT];
    int wcnt = 0;
    #pragma unroll
    for (int k = 0; k < CPT; k++) {
        bool valid = (base + k * THREADS + tid) < total_cells;
        float cx = s_conf[ridx[k]][2 * lidx[k]];
        float cy = s_conf[ridx[k]][2 * lidx[k] + 1];
        if (valid) vbase += NOOBJ_W * (cx * cx + cy * cy);
        bal[k] = __ballot_sync(0xffffffffu, valid && (flag[k] != 0.0f));
        wcnt  += __popc(bal[k]);
    }
    if (lane == 0) s_wcnt[wid] = wcnt;
    __syncthreads();

    int woff = 0, total_obj = 0;
    #pragma unroll
    for (int w = 0; w < NWARPS; w++) {
        int c = s_wcnt[w];
        if (w < wid) woff += c;
        total_obj += c;
    }
    int pfx = woff;
    #pragma unroll
    for (int k = 0; k < CPT; k++) {
        bool o = (bal[k] >> lane) & 1u;
        int pos = pfx + __popc(bal[k] & lmask);
        if (o) s_idx[pos] = k * THREADS + tid;
        pfx += __popc(bal[k]);
    }
    __syncthreads();

    // ---- phase 2: chunked gather + dense compute ---------------------------
    double vd = (double)vbase;
    const int role = tid & 15;

    for (int cs = 0; cs < total_obj; cs += CHUNK) {
        int cnt = min(CHUNK, total_obj - cs);
        int npass = (cnt + 15) >> 4;

        // -- gather: 16 threads per cell, float4 aligned windows --
        for (int pass = 0; pass < npass; pass++) {
            int ci = pass * 16 + (tid >> 4);
            if (ci < cnt) {
                int cell = base + s_idx[cs + ci];
                int i = cell / L_CELLS, l = cell - i * L_CELLS;

                unsigned wbase; const float* src; unsigned nf;
                int slot, dbase, dcount;
                if (role < 7) {
                    wbase = (unsigned)i * ROW_L + 25u * l;
                    src = labels; nf = (unsigned)nlab_floats;
                    slot = role;       dbase = 0;  dcount = 25;
                } else if (role < 13) {
                    wbase = (unsigned)i * ROW_P + 20u * l;
                    src = preds; nf = (unsigned)npred_floats;
                    slot = role - 7;   dbase = 25; dcount = 20;
                } else {
                    wbase = (unsigned)i * ROW_P + 1078u + 8u * l;
                    src = preds; nf = (unsigned)npred_floats;
                    slot = role - 13;  dbase = 45; dcount = 8;
                }
                unsigned a   = wbase & ~3u;
                int      off = (int)(wbase & 3u);
                unsigned w0  = a + 4u * slot;
                float4 v = make_float4(0.f, 0.f, 0.f, 0.f);
                if (w0 < nf)
                    v = __ldg(reinterpret_cast<const float4*>(src + w0));
                float vv[4] = {v.x, v.y, v.z, v.w};
                int d0 = 4 * slot - off;
                #pragma unroll
                for (int w = 0; w < 4; w++) {
                    int d = d0 + w;
                    if (d >= 0 && d < dcount) s_cell[ci][dbase + d] = vv[w];
                }
            }
        }
        __syncthreads();

        // -- compute: one thread per staged cell, operands from smem --
        if (tid < cnt) {
            int cell = base + s_idx[cs + tid];
            int i = cell / L_CELLS, l = cell - i * L_CELLS;
            const float* cd = s_cell[tid];

            float pcx = s_conf[i - rfirst][2 * l];
            float pcy = s_conf[i - rfirst][2 * l + 1];

            float tb0 = cd[21], tb1 = cd[22], tb2 = cd[23], tb3 = cd[24];

            float cls = 0.0f;
            #pragma unroll
            for (int c = 0; c < 20; c++) {
                float d = cd[1 + c] - cd[25 + c];
                cls += d * d;
            }
            cls *= CLS_W;

            float b0x = cd[45], b0y = cd[46], b0w = cd[47], b0h = cd[48];
            float b1x = cd[49], b1y = cd[50], b1w = cd[51], b1h = cd[52];

            float o0x = b0x * (1.0f / 7.0f), o0y = b0y * (1.0f / 7.0f);
            float o0w = b0w * b0w,           o0h = b0h * b0h;
            float o1x = b1x * (1.0f / 7.0f), o1y = b1y * (1.0f / 7.0f);
            float o1w = b1w * b1w,           o1h = b1h * b1h;
            float tx = tb0 * (1.0f / 7.0f), ty = tb1 * (1.0f / 7.0f);
            float tw = tb2, th = tb3;

            float iou0, iou1, r0, r1;
            {
                float left   = fmaxf(tx - 0.5f * tw, o0x - 0.5f * o0w);
                float right  = fminf(tx + 0.5f * tw, o0x + 0.5f * o0w);
                float top    = fmaxf(ty - 0.5f * th, o0y - 0.5f * o0h);
                float bottom = fminf(ty + 0.5f * th, o0y + 0.5f * o0h);
                float w = right - left, h = bottom - top;
                bool invalid = (w < 0.0f) || (h < 0.0f);
                float inter = invalid ? 0.0f : w * h;
                float uni = tw * th + o0w * o0h - inter;
                iou0 = invalid ? 0.0f : inter / fmaxf(uni, 1e-12f);
                float d0 = tx - o0x, d1 = ty - o0y, d2 = tw - o0w, d3 = th - o0h;
                r0 = d0 * d0 + d1 * d1 + d2 * d2 + d3 * d3;
            }
            {
                float left   = fmaxf(tx - 0.5f * tw, o1x - 0.5f * o1w);
                float right  = fminf(tx + 0.5f * tw, o1x + 0.5f * o1w);
                float top    = fmaxf(ty - 0.5f * th, o1y - 0.5f * o1h);
                float bottom = fminf(ty + 0.5f * th, o1y + 0.5f * o1h);
                float w = right - left, h = bottom - top;
                bool invalid = (w < 0.0f) || (h < 0.0f);
                float inter = invalid ? 0.0f : w * h;
                float uni = tw * th + o1w * o1h - inter;
                iou1 = invalid ? 0.0f : inter / fmaxf(uni, 1e-12f);
                float d0 = tx - o1x, d1 = ty - o1y, d2 = tw - o1w, d3 = th - o1h;
                r1 = d0 * d0 + d1 * d1 + d2 * d2 + d3 * d3;
            }

            float miou = fmaxf(iou0, iou1);
            int best = (miou > 0.0f) ? ((iou1 > iou0) ? 1 : 0)
                                     : ((r1 < r0) ? 1 : 0);

            float best_iou  = best ? iou1 : iou0;
            float conf_best = best ? pcy : pcx;
            float dcb = best_iou - conf_best;
            float conf_corr = OBJ_W * dcb * dcb - NOOBJ_W * conf_best * conf_best;

            float pbx = best ? b1x : b0x;
            float pby = best ? b1y : b0y;
            float pbw = best ? b1w : b0w;
            float pbh = best ? b1h : b0h;
            float st2 = sqrtf(tb2), st3 = sqrtf(tb3);
            float e0 = tb0 - pbx, e1 = tb1 - pby;
            float e2 = st2 - pbw, e3 = st3 - pbh;
            float coord = COORD_W * (e0 * e0 + e1 * e1 + e2 * e2 + e3 * e3);

            vd += (double)(conf_corr + cls + coord);
        }
        __syncthreads();   // protect s_cell before next chunk
    }

    // ---- block reduction ----------------------------------------------------
    #pragma unroll
    for (int off = 16; off > 0; off >>= 1)
        vd += __shfl_down_sync(0xffffffffu, vd, off);
    if (lane == 0) s_red[wid] = vd;
    __syncthreads();

    if (wid == 0) {
        double x = (lane < NWARPS) ? s_red[lane] : 0.0;
        #pragma unroll
        for (int off = 4; off > 0; off >>= 1)
            x += __shfl_down_sync(0xffffffffu, x, off);
        if (lane == 0) g_partials[blockIdx.x] = x;
    }
    __syncthreads();

    // ---- fused finalize: last block reduces all partials --------------------
    if (tid == 0) {
        __threadfence();
        unsigned old = atomicInc(&g_counter, gridDim.x - 1);
        s_last = (old == gridDim.x - 1);
    }
    __syncthreads();

    if (s_last) {
        __threadfence();
        double s = 0.0;
        for (int i = tid; i < gridDim.x; i += THREADS)
            s += g_partials[i];
        #pragma unroll
        for (int off = 16; off > 0; off >>= 1)
            s += __shfl_down_sync(0xffffffffu, s, off);
        if (lane == 0) s_red[wid] = s;
        __syncthreads();
        if (wid == 0) {
            double x = (lane < NWARPS) ? s_red[lane] : 0.0;
            #pragma unroll
            for (int off = 4; off > 0; off >>= 1)
                x += __shfl_down_sync(0xffffffffu, x, off);
            if (lane == 0) out[0] = (float)x;
        }
    }
}

extern "C" void kernel_launch(void* const* d_in, const int* in_sizes, int n_in,
                              void* d_out, int out_size)
{
    const float* preds  = (const float*)d_in[0];
    const float* labels = (const float*)d_in[1];
    int n = in_sizes[0] / ROW_P;
    int total_cells = n * L_CELLS;

    int blocks = (total_cells + CPB - 1) / CPB;   // n=16384 -> 1568 blocks
    if (blocks > MAX_BLOCKS) blocks = MAX_BLOCKS;

    yolo_loss_kernel<<<blocks, THREADS>>>(preds, labels, total_cells,
                                          in_sizes[1], in_sizes[0],
                                          (float*)d_out);
}

// round 7
// speedup vs baseline: 1.4747x; 1.4747x over previous
#include <cuda_runtime.h>

// YOLO-style detection loss — per-warp compaction, barrier-free mainline.
// preds:  (n, 1470) f32  [pcls 980 | pconf 98 | pbox 392]
// labels: (n, 1225) f32  per cell (25 floats): [flag | 20 cls | 4 box]
// Row bases only 8B-aligned for odd rows => vector loads are float2 max.

#define L_CELLS 49
#define ROW_P 1470
#define ROW_L 1225
#define NOOBJ_W 0.5f
#define OBJ_W 0.5f
#define CLS_W 0.5f
#define COORD_W 2.5f

#define THREADS 256
#define CPT 4
#define CPB (THREADS * CPT)
#define NWARPS (THREADS / 32)
#define MAX_BLOCKS 8192

__device__ double   g_partials[MAX_BLOCKS];
__device__ unsigned g_counter = 0;    // self-wrapping; replay-safe

__device__ __forceinline__ float obj_cell_loss(
    const float* __restrict__ preds,
    const float* __restrict__ labels,
    int cell)
{
    int i = cell / L_CELLS;
    int l = cell - i * L_CELLS;
    const float* p  = preds  + (size_t)i * ROW_P;
    const float* lb = labels + (size_t)i * ROW_L + l * 25;

    // ---- issue all loads up front ----
    float2 pc = __ldg(reinterpret_cast<const float2*>(p + 980 + l * 2));

    float tb0 = __ldg(lb + 21);
    float tb1 = __ldg(lb + 22);
    float tb2 = __ldg(lb + 23);
    float tb3 = __ldg(lb + 24);

    const float* pb = p + 1078 + l * 8;       // 8B aligned
    float2 b01 = __ldg(reinterpret_cast<const float2*>(pb + 0));
    float2 b23 = __ldg(reinterpret_cast<const float2*>(pb + 2));
    float2 b45 = __ldg(reinterpret_cast<const float2*>(pb + 4));
    float2 b67 = __ldg(reinterpret_cast<const float2*>(pb + 6));

    // ---- class loss (float2 only; l*20 even -> 8B aligned) ----
    const float* pcl = p + l * 20;
    float cls = 0.0f;
    #pragma unroll
    for (int c = 0; c < 20; c += 2) {
        float2 pv = __ldg(reinterpret_cast<const float2*>(pcl + c));
        float d0 = __ldg(lb + 1 + c) - pv.x;
        float d1 = __ldg(lb + 2 + c) - pv.y;
        cls += d0 * d0 + d1 * d1;
    }
    cls *= CLS_W;

    // transformed: o = [x/S, y/S, w^2, h^2]; t = [x/S, y/S, w, h]
    float o0x = b01.x * (1.0f / 7.0f), o0y = b01.y * (1.0f / 7.0f);
    float o0w = b23.x * b23.x,         o0h = b23.y * b23.y;
    float o1x = b45.x * (1.0f / 7.0f), o1y = b45.y * (1.0f / 7.0f);
    float o1w = b67.x * b67.x,         o1h = b67.y * b67.y;
    float tx = tb0 * (1.0f / 7.0f), ty = tb1 * (1.0f / 7.0f);
    float tw = tb2, th = tb3;

    float iou0, iou1, r0, r1;
    {
        float left   = fmaxf(tx - 0.5f * tw, o0x - 0.5f * o0w);
        float right  = fminf(tx + 0.5f * tw, o0x + 0.5f * o0w);
        float top    = fmaxf(ty - 0.5f * th, o0y - 0.5f * o0h);
        float bottom = fminf(ty + 0.5f * th, o0y + 0.5f * o0h);
        float w = right - left, h = bottom - top;
        bool invalid = (w < 0.0f) || (h < 0.0f);
        float inter = invalid ? 0.0f : w * h;
        float uni = tw * th + o0w * o0h - inter;
        iou0 = invalid ? 0.0f : inter / fmaxf(uni, 1e-12f);
        float d0 = tx - o0x, d1 = ty - o0y, d2 = tw - o0w, d3 = th - o0h;
        r0 = d0 * d0 + d1 * d1 + d2 * d2 + d3 * d3;
    }
    {
        float left   = fmaxf(tx - 0.5f * tw, o1x - 0.5f * o1w);
        float right  = fminf(tx + 0.5f * tw, o1x + 0.5f * o1w);
        float top    = fmaxf(ty - 0.5f * th, o1y - 0.5f * o1h);
        float bottom = fminf(ty + 0.5f * th, o1y + 0.5f * o1h);
        float w = right - left, h = bottom - top;
        bool invalid = (w < 0.0f) || (h < 0.0f);
        float inter = invalid ? 0.0f : w * h;
        float uni = tw * th + o1w * o1h - inter;
        iou1 = invalid ? 0.0f : inter / fmaxf(uni, 1e-12f);
        float d0 = tx - o1x, d1 = ty - o1y, d2 = tw - o1w, d3 = th - o1h;
        r1 = d0 * d0 + d1 * d1 + d2 * d2 + d3 * d3;
    }

    // argmax/argmin first-index tie semantics
    float miou = fmaxf(iou0, iou1);
    int best = (miou > 0.0f) ? ((iou1 > iou0) ? 1 : 0)
                             : ((r1 < r0) ? 1 : 0);

    float best_iou  = best ? iou1 : iou0;
    float conf_best = best ? pc.y : pc.x;
    float dcb = best_iou - conf_best;
    // correction vs unconditional NOOBJ*(cx^2+cy^2) base from phase 1
    float conf_corr = OBJ_W * dcb * dcb - NOOBJ_W * conf_best * conf_best;

    float pbx = best ? b45.x : b01.x;
    float pby = best ? b45.y : b01.y;
    float pbw = best ? b67.x : b23.x;
    float pbh = best ? b67.y : b23.y;
    float st2 = sqrtf(tb2), st3 = sqrtf(tb3);
    float e0 = tb0 - pbx, e1 = tb1 - pby;
    float e2 = st2 - pbw, e3 = st3 - pbh;
    float coord = COORD_W * (e0 * e0 + e1 * e1 + e2 * e2 + e3 * e3);

    return conf_corr + cls + coord;
}

__global__ void __launch_bounds__(THREADS) yolo_loss_kernel(
    const float* __restrict__ preds,
    const float* __restrict__ labels,
    int total_cells,
    float* __restrict__ out)
{
    __shared__ double s_red[NWARPS];
    __shared__ bool   s_last;

    const int tid  = threadIdx.x;
    const int lane = tid & 31;
    const int wid  = tid >> 5;
    const int base = blockIdx.x * CPB;
    const int wbase = wid * 32;      // warp's lane-0 offset within a k-chunk

    // ===== phase 1: flags + pconf, front-batched (MLP = 8) ==================
    float  flag[CPT];
    float2 pc[CPT];
    bool   valid[CPT];

    #pragma unroll
    for (int k = 0; k < CPT; k++) {
        int cell = base + k * THREADS + tid;
        valid[k] = cell < total_cells;
        int c = valid[k] ? cell : 0;
        int i = c / L_CELLS, l = c - (c / L_CELLS) * L_CELLS;
        flag[k] = __ldg(labels + (size_t)i * ROW_L + 25 * l);
        pc[k]   = __ldg(reinterpret_cast<const float2*>(
                        preds + (size_t)i * ROW_P + 980 + 2 * l));
    }

    float vbase = 0.0f;
    unsigned bal[CPT];
    int T = 0;                        // obj cells in this warp's 128 cells
    #pragma unroll
    for (int k = 0; k < CPT; k++) {
        if (valid[k])
            vbase += NOOBJ_W * (pc[k].x * pc[k].x + pc[k].y * pc[k].y);
        bal[k] = __ballot_sync(0xffffffffu, valid[k] && (flag[k] != 0.0f));
        T += __popc(bal[k]);
    }

    // ===== phase 2: per-warp obj processing (no barriers, no smem) ==========
    double vd = (double)vbase;
    for (int t = lane; t < T; t += 32) {
        int j = t;
        int cellLocal = 0;
        #pragma unroll
        for (int k = 0; k < CPT; k++) {
            int c = __popc(bal[k]);
            if (j >= 0 && j < c) {
                int pos = __fns(bal[k], 0, j + 1);
                cellLocal = k * THREADS + wbase + pos;
            }
            j -= c;
        }
        vd += (double)obj_cell_loss(preds, labels, base + cellLocal);
    }

    // ===== block reduction ===================================================
    #pragma unroll
    for (int off = 16; off > 0; off >>= 1)
        vd += __shfl_down_sync(0xffffffffu, vd, off);
    if (lane == 0) s_red[wid] = vd;
    __syncthreads();

    if (wid == 0) {
        double x = (lane < NWARPS) ? s_red[lane] : 0.0;
        #pragma unroll
        for (int off = 4; off > 0; off >>= 1)
            x += __shfl_down_sync(0xffffffffu, x, off);
        if (lane == 0) g_partials[blockIdx.x] = x;
    }
    __syncthreads();

    // ===== fused finalize: last block reduces all partials ===================
    if (tid == 0) {
        __threadfence();
        unsigned old = atomicInc(&g_counter, gridDim.x - 1);
        s_last = (old == gridDim.x - 1);
    }
    __syncthreads();

    if (s_last) {
        __threadfence();
        double s = 0.0;
        for (int i = tid; i < gridDim.x; i += THREADS)
            s += g_partials[i];
        #pragma unroll
        for (int off = 16; off > 0; off >>= 1)
            s += __shfl_down_sync(0xffffffffu, s, off);
        if (lane == 0) s_red[wid] = s;
        __syncthreads();
        if (wid == 0) {
            double x = (lane < NWARPS) ? s_red[lane] : 0.0;
            #pragma unroll
            for (int off = 4; off > 0; off >>= 1)
                x += __shfl_down_sync(0xffffffffu, x, off);
            if (lane == 0) out[0] = (float)x;
        }
    }
}

extern "C" void kernel_launch(void* const* d_in, const int* in_sizes, int n_in,
                              void* d_out, int out_size)
{
    const float* preds  = (const float*)d_in[0];
    const float* labels = (const float*)d_in[1];
    int n = in_sizes[0] / ROW_P;
    int total_cells = n * L_CELLS;

    int blocks = (total_cells + CPB - 1) / CPB;   // n=16384 -> 784 blocks
    if (blocks > MAX_BLOCKS) blocks = MAX_BLOCKS;

    yolo_loss_kernel<<<blocks, THREADS>>>(preds, labels, total_cells,
                                          (float*)d_out);
}